// round 6
// baseline (speedup 1.0000x reference)
#include <cuda_runtime.h>
#include <math.h>

// CapsuleLayer dynamic routing v5 (resubmit after infra failure): v4 structure
// + pairwise-interleaved FFMA2 (shared x operand between adjacent issues ->
// lower RF-bank rt), merged route kernel (bcomb+esum), float4-vectorized squash.

#define BB 64
#define NN 2304
#define CC 32
#define OO 16
#define II 8
#define CO 512
#define WROW 4096     // C*O*I floats per n
#define NCHUNK 72
#define NPC 32        // NN / NCHUNK
#define BG 16         // batch rows per block
#define BP 8          // b-pairs per block
#define NBG 4

__device__ float g_spart[(size_t)NCHUNK * BB * CO];  // 9.4 MB
__device__ float g_v[BB * CO];
__device__ float g_bupd[NBG * NN * CC];
__device__ float g_b[NN * CC];
__device__ float g_e[NN * CC];
__device__ float g_inv[CC];

typedef unsigned long long u64;

__device__ __forceinline__ u64 pk2(float lo, float hi) {
    u64 r; asm("mov.b64 %0,{%1,%2};" : "=l"(r) : "f"(lo), "f"(hi)); return r;
}
__device__ __forceinline__ float2 unpk(u64 v) {
    float2 r; asm("mov.b64 {%0,%1},%2;" : "=f"(r.x), "=f"(r.y) : "l"(v)); return r;
}
__device__ __forceinline__ u64 ffma2(u64 a, u64 b, u64 c) {
    u64 d; asm("fma.rn.f32x2 %0,%1,%2,%3;" : "=l"(d) : "l"(a), "l"(b), "l"(c)); return d;
}
__device__ __forceinline__ u64 fmul2(u64 a, u64 b) {
    u64 d; asm("mul.rn.f32x2 %0,%1,%2;" : "=l"(d) : "l"(a), "l"(b)); return d;
}

// shared x tile: xs[ipair(4)][bp(8)][nn(32)] of ulonglong2 = 16KB
#define XS_LOAD(xs, x4, bg, n0, t)                                              \
    {                                                                            \
        int bp = (t) >> 5;                                                       \
        int nn = (t) & 31;                                                       \
        const float4* xp0 = (x4) + ((size_t)((bg) * BG + 2 * bp) * NN + ((n0) + nn)) * 2; \
        const float4* xp1 = (x4) + ((size_t)((bg) * BG + 2 * bp + 1) * NN + ((n0) + nn)) * 2; \
        float4 a0 = xp0[0], a1 = xp0[1];                                         \
        float4 c0 = xp1[0], c1 = xp1[1];                                         \
        xs[0][bp][nn] = make_ulonglong2(pk2(a0.x, c0.x), pk2(a0.y, c0.y));       \
        xs[1][bp][nn] = make_ulonglong2(pk2(a0.z, c0.z), pk2(a0.w, c0.w));       \
        xs[2][bp][nn] = make_ulonglong2(pk2(a1.x, c1.x), pk2(a1.y, c1.y));       \
        xs[3][bp][nn] = make_ulonglong2(pk2(a1.z, c1.z), pk2(a1.w, c1.w));       \
    }

// ---------------------------------------------------------------------------
// k_sj: s partials. block = (n-chunk of 32, b-group of 16); 256 threads.
// Thread owns co pair (2t,2t+1); acc lanes are b-pairs. a0/a1 FFMA2s are
// pairwise interleaved so adjacent issues share the x operand.
// ---------------------------------------------------------------------------
__global__ __launch_bounds__(256, 2)
void k_sj(const float* __restrict__ x, const float* __restrict__ W, int use_e)
{
    const int chunk = blockIdx.x;
    const int bg    = blockIdx.y;
    const int t     = threadIdx.x;
    const int n0    = chunk * NPC;
    const int c     = t >> 3;

    __shared__ ulonglong2 xs[4][BP][NPC];   // 16KB
    __shared__ float es[NPC * CC];          // 4KB

    const float4* x4 = (const float4*)x;
    XS_LOAD(xs, x4, bg, n0, t);
    if (use_e) {
        for (int idx = t; idx < NPC * CC; idx += 256)
            es[idx] = g_e[(size_t)n0 * CC + idx];
    }
    __syncthreads();

    u64 acc0[BP], acc1[BP];
#pragma unroll
    for (int bp = 0; bp < BP; bp++) { acc0[bp] = 0ull; acc1[bp] = 0ull; }

    const float4* wp = (const float4*)(W + (size_t)n0 * WROW + (size_t)(2 * t) * II);
    float4 wa0 = wp[0], wa1 = wp[1], wb0 = wp[2], wb1 = wp[3];

    for (int nn = 0; nn < NPC; nn++) {
        float cw = use_e ? es[nn * CC + c] : (1.0f / (float)NN);
        u64 wc0[8], wc1[8];
        {
            float m;
            m = wa0.x * cw; wc0[0] = pk2(m, m);
            m = wa0.y * cw; wc0[1] = pk2(m, m);
            m = wa0.z * cw; wc0[2] = pk2(m, m);
            m = wa0.w * cw; wc0[3] = pk2(m, m);
            m = wa1.x * cw; wc0[4] = pk2(m, m);
            m = wa1.y * cw; wc0[5] = pk2(m, m);
            m = wa1.z * cw; wc0[6] = pk2(m, m);
            m = wa1.w * cw; wc0[7] = pk2(m, m);
            m = wb0.x * cw; wc1[0] = pk2(m, m);
            m = wb0.y * cw; wc1[1] = pk2(m, m);
            m = wb0.z * cw; wc1[2] = pk2(m, m);
            m = wb0.w * cw; wc1[3] = pk2(m, m);
            m = wb1.x * cw; wc1[4] = pk2(m, m);
            m = wb1.y * cw; wc1[5] = pk2(m, m);
            m = wb1.z * cw; wc1[6] = pk2(m, m);
            m = wb1.w * cw; wc1[7] = pk2(m, m);
        }
        if (nn + 1 < NPC) {
            const float4* wn = wp + (size_t)(nn + 1) * (WROW / 4);
            wa0 = wn[0]; wa1 = wn[1]; wb0 = wn[2]; wb1 = wn[3];
        }
#pragma unroll
        for (int bp = 0; bp < BP; bp++) {
            ulonglong2 x01 = xs[0][bp][nn];
            ulonglong2 x23 = xs[1][bp][nn];
            ulonglong2 x45 = xs[2][bp][nn];
            ulonglong2 x67 = xs[3][bp][nn];
            u64 a0 = acc0[bp], a1 = acc1[bp];
            // pairwise interleave: adjacent instrs share the x operand
            a0 = ffma2(wc0[0], x01.x, a0); a1 = ffma2(wc1[0], x01.x, a1);
            a0 = ffma2(wc0[1], x01.y, a0); a1 = ffma2(wc1[1], x01.y, a1);
            a0 = ffma2(wc0[2], x23.x, a0); a1 = ffma2(wc1[2], x23.x, a1);
            a0 = ffma2(wc0[3], x23.y, a0); a1 = ffma2(wc1[3], x23.y, a1);
            a0 = ffma2(wc0[4], x45.x, a0); a1 = ffma2(wc1[4], x45.x, a1);
            a0 = ffma2(wc0[5], x45.y, a0); a1 = ffma2(wc1[5], x45.y, a1);
            a0 = ffma2(wc0[6], x67.x, a0); a1 = ffma2(wc1[6], x67.x, a1);
            a0 = ffma2(wc0[7], x67.y, a0); a1 = ffma2(wc1[7], x67.y, a1);
            acc0[bp] = a0; acc1[bp] = a1;
        }
    }

    float* sp = g_spart + ((size_t)chunk * BB + (size_t)bg * BG) * CO + 2 * t;
#pragma unroll
    for (int bp = 0; bp < BP; bp++) {
        float2 f0 = unpk(acc0[bp]);   // (s[b0,co0], s[b1,co0])
        float2 f1 = unpk(acc1[bp]);   // (s[b0,co1], s[b1,co1])
        *(float2*)(sp + (size_t)(2 * bp) * CO)     = make_float2(f0.x, f1.x);
        *(float2*)(sp + (size_t)(2 * bp + 1) * CO) = make_float2(f0.y, f1.y);
    }
}

// ---------------------------------------------------------------------------
// k_bupd: agreement partials; recompute t per n, dot with v (b-pair packed).
// ---------------------------------------------------------------------------
__global__ __launch_bounds__(256, 2)
void k_bupd(const float* __restrict__ x, const float* __restrict__ W)
{
    const int chunk = blockIdx.x;
    const int bg    = blockIdx.y;
    const int t     = threadIdx.x;
    const int n0    = chunk * NPC;

    __shared__ ulonglong2 xs[4][BP][NPC];   // 16KB

    const float4* x4 = (const float4*)x;
    XS_LOAD(xs, x4, bg, n0, t);
    __syncthreads();

    u64 vp0[BP], vp1[BP];
#pragma unroll
    for (int bp = 0; bp < BP; bp++) {
        const float* v0 = g_v + (size_t)(bg * BG + 2 * bp) * CO + 2 * t;
        const float* v1 = g_v + (size_t)(bg * BG + 2 * bp + 1) * CO + 2 * t;
        float2 a = *(const float2*)v0;   // (v[b0,co0], v[b0,co1])
        float2 b = *(const float2*)v1;
        vp0[bp] = pk2(a.x, b.x);         // (v[b0,co0], v[b1,co0])
        vp1[bp] = pk2(a.y, b.y);         // (v[b0,co1], v[b1,co1])
    }

    const float4* wp = (const float4*)(W + (size_t)n0 * WROW + (size_t)(2 * t) * II);
    float4 wa0 = wp[0], wa1 = wp[1], wb0 = wp[2], wb1 = wp[3];

    for (int nn = 0; nn < NPC; nn++) {
        u64 wd0[8], wd1[8];
        wd0[0] = pk2(wa0.x, wa0.x); wd0[1] = pk2(wa0.y, wa0.y);
        wd0[2] = pk2(wa0.z, wa0.z); wd0[3] = pk2(wa0.w, wa0.w);
        wd0[4] = pk2(wa1.x, wa1.x); wd0[5] = pk2(wa1.y, wa1.y);
        wd0[6] = pk2(wa1.z, wa1.z); wd0[7] = pk2(wa1.w, wa1.w);
        wd1[0] = pk2(wb0.x, wb0.x); wd1[1] = pk2(wb0.y, wb0.y);
        wd1[2] = pk2(wb0.z, wb0.z); wd1[3] = pk2(wb0.w, wb0.w);
        wd1[4] = pk2(wb1.x, wb1.x); wd1[5] = pk2(wb1.y, wb1.y);
        wd1[6] = pk2(wb1.z, wb1.z); wd1[7] = pk2(wb1.w, wb1.w);
        if (nn + 1 < NPC) {
            const float4* wn = wp + (size_t)(nn + 1) * (WROW / 4);
            wa0 = wn[0]; wa1 = wn[1]; wb0 = wn[2]; wb1 = wn[3];
        }
        u64 pacc = 0ull;
#pragma unroll
        for (int bp = 0; bp < BP; bp++) {
            ulonglong2 x01 = xs[0][bp][nn];
            ulonglong2 x23 = xs[1][bp][nn];
            ulonglong2 x45 = xs[2][bp][nn];
            ulonglong2 x67 = xs[3][bp][nn];
            u64 t0 = fmul2(wd0[0], x01.x);
            u64 t1 = fmul2(wd1[0], x01.x);
            t0 = ffma2(wd0[1], x01.y, t0); t1 = ffma2(wd1[1], x01.y, t1);
            t0 = ffma2(wd0[2], x23.x, t0); t1 = ffma2(wd1[2], x23.x, t1);
            t0 = ffma2(wd0[3], x23.y, t0); t1 = ffma2(wd1[3], x23.y, t1);
            t0 = ffma2(wd0[4], x45.x, t0); t1 = ffma2(wd1[4], x45.x, t1);
            t0 = ffma2(wd0[5], x45.y, t0); t1 = ffma2(wd1[5], x45.y, t1);
            t0 = ffma2(wd0[6], x67.x, t0); t1 = ffma2(wd1[6], x67.x, t1);
            t0 = ffma2(wd0[7], x67.y, t0); t1 = ffma2(wd1[7], x67.y, t1);
            pacc = ffma2(t0, vp0[bp], pacc);
            pacc = ffma2(t1, vp1[bp], pacc);
        }
        float2 pv = unpk(pacc);
        float p = pv.x + pv.y;
        p += __shfl_down_sync(0xffffffffu, p, 4, 8);
        p += __shfl_down_sync(0xffffffffu, p, 2, 8);
        p += __shfl_down_sync(0xffffffffu, p, 1, 8);
        if ((t & 7) == 0)
            g_bupd[(size_t)bg * (NN * CC) + (size_t)(n0 + nn) * CC + (t >> 3)] = p;
    }
}

// ---------------------------------------------------------------------------
// k_squash: float4-vectorized partial reduce + squash. 8192 float4 ids.
// ---------------------------------------------------------------------------
__global__ void k_squash(float* __restrict__ dout, int uniform, int final_pass)
{
    int id4 = blockIdx.x * 256 + threadIdx.x;   // 0..8191
    const float4* sp = (const float4*)g_spart;
    float4 s0 = make_float4(0.f, 0.f, 0.f, 0.f);
    float4 s1 = make_float4(0.f, 0.f, 0.f, 0.f);
#pragma unroll 4
    for (int ch = 0; ch < NCHUNK; ch += 2) {
        float4 p0 = sp[(size_t)ch * 8192 + id4];
        float4 p1 = sp[(size_t)(ch + 1) * 8192 + id4];
        s0.x += p0.x; s0.y += p0.y; s0.z += p0.z; s0.w += p0.w;
        s1.x += p1.x; s1.y += p1.y; s1.z += p1.z; s1.w += p1.w;
    }
    float4 s = make_float4(s0.x + s1.x, s0.y + s1.y, s0.z + s1.z, s0.w + s1.w);
    int c = (id4 >> 2) & 31;
    float scale = uniform ? 1.0f : g_inv[c];
    s.x *= scale; s.y *= scale; s.z *= scale; s.w *= scale;
    float4 v;
    v.x = s.x * fabsf(s.x) / (1.0f + s.x * s.x);
    v.y = s.y * fabsf(s.y) / (1.0f + s.y * s.y);
    v.z = s.z * fabsf(s.z) / (1.0f + s.z * s.z);
    v.w = s.w * fabsf(s.w) / (1.0f + s.w * s.w);
    if (final_pass) ((float4*)dout)[id4] = v;
    else            ((float4*)g_v)[id4]  = v;
}

// ---------------------------------------------------------------------------
// k_route: combine agreement partials -> b update -> e = exp(b) -> per-c
// e-sum reciprocal. One block per c.
// ---------------------------------------------------------------------------
__global__ void k_route(int iter0)
{
    const int c = blockIdx.x;
    const int t = threadIdx.x;
    __shared__ float red[256];

    float local = 0.0f;
    for (int n = t; n < NN; n += 256) {
        size_t idx = (size_t)n * CC + c;
        float a = g_bupd[idx]
                + g_bupd[(size_t)NN * CC + idx]
                + g_bupd[(size_t)2 * NN * CC + idx]
                + g_bupd[(size_t)3 * NN * CC + idx];
        a *= (1.0f / (float)BB);
        float bb = iter0 ? a : (g_b[idx] + a);
        g_b[idx] = bb;
        float e = expf(bb);
        g_e[idx] = e;
        local += e;
    }
    red[t] = local;
    __syncthreads();
    for (int off = 128; off > 0; off >>= 1) {
        if (t < off) red[t] += red[t + off];
        __syncthreads();
    }
    if (t == 0) g_inv[c] = 1.0f / red[0];
}

// ---------------------------------------------------------------------------
extern "C" void kernel_launch(void* const* d_in, const int* in_sizes, int n_in,
                              void* d_out, int out_size)
{
    const float* x = (const float*)d_in[0];   // [B, N, I]
    const float* W = (const float*)d_in[1];   // [N, C, O, I]
    float* out = (float*)d_out;               // [B, C, O, 1]

    dim3 g(NCHUNK, NBG);

    // iteration 0 (uniform weights 1/N inside k_sj)
    k_sj<<<g, 256>>>(x, W, 0);
    k_squash<<<32, 256>>>(out, 1, 0);
    k_bupd<<<g, 256>>>(x, W);
    k_route<<<CC, 256>>>(1);

    // iteration 1 (weights = exp(b), normalized in squash)
    k_sj<<<g, 256>>>(x, W, 1);
    k_squash<<<32, 256>>>(out, 0, 0);
    k_bupd<<<g, 256>>>(x, W);
    k_route<<<CC, 256>>>(0);

    // iteration 2 (final)
    k_sj<<<g, 256>>>(x, W, 1);
    k_squash<<<32, 256>>>(out, 0, 1);
}

// round 8
// speedup vs baseline: 1.1492x; 1.1492x over previous
#include <cuda_runtime.h>
#include <math.h>

// CapsuleLayer dynamic routing v6 (resubmit after infra failure): v4
// small-kernel structure (coalesced bcomb + esum) restored, v5 interleaved
// FFMA2 heavies kept, squash re-gridded to 128 blocks with float2 loads.

#define BB 64
#define NN 2304
#define CC 32
#define OO 16
#define II 8
#define CO 512
#define WROW 4096     // C*O*I floats per n
#define NCHUNK 72
#define NPC 32        // NN / NCHUNK
#define BG 16         // batch rows per block
#define BP 8          // b-pairs per block
#define NBG 4

__device__ float g_spart[(size_t)NCHUNK * BB * CO];  // 9.4 MB
__device__ float g_v[BB * CO];
__device__ float g_bupd[NBG * NN * CC];
__device__ float g_b[NN * CC];
__device__ float g_e[NN * CC];
__device__ float g_epart[288 * CC];
__device__ float g_inv[CC];

typedef unsigned long long u64;

__device__ __forceinline__ u64 pk2(float lo, float hi) {
    u64 r; asm("mov.b64 %0,{%1,%2};" : "=l"(r) : "f"(lo), "f"(hi)); return r;
}
__device__ __forceinline__ float2 unpk(u64 v) {
    float2 r; asm("mov.b64 {%0,%1},%2;" : "=f"(r.x), "=f"(r.y) : "l"(v)); return r;
}
__device__ __forceinline__ u64 ffma2(u64 a, u64 b, u64 c) {
    u64 d; asm("fma.rn.f32x2 %0,%1,%2,%3;" : "=l"(d) : "l"(a), "l"(b), "l"(c)); return d;
}
__device__ __forceinline__ u64 fmul2(u64 a, u64 b) {
    u64 d; asm("mul.rn.f32x2 %0,%1,%2;" : "=l"(d) : "l"(a), "l"(b)); return d;
}

// shared x tile: xs[ipair(4)][bp(8)][nn(32)] of ulonglong2 = 16KB
#define XS_LOAD(xs, x4, bg, n0, t)                                              \
    {                                                                            \
        int bp = (t) >> 5;                                                       \
        int nn = (t) & 31;                                                       \
        const float4* xp0 = (x4) + ((size_t)((bg) * BG + 2 * bp) * NN + ((n0) + nn)) * 2; \
        const float4* xp1 = (x4) + ((size_t)((bg) * BG + 2 * bp + 1) * NN + ((n0) + nn)) * 2; \
        float4 a0 = xp0[0], a1 = xp0[1];                                         \
        float4 c0 = xp1[0], c1 = xp1[1];                                         \
        xs[0][bp][nn] = make_ulonglong2(pk2(a0.x, c0.x), pk2(a0.y, c0.y));       \
        xs[1][bp][nn] = make_ulonglong2(pk2(a0.z, c0.z), pk2(a0.w, c0.w));       \
        xs[2][bp][nn] = make_ulonglong2(pk2(a1.x, c1.x), pk2(a1.y, c1.y));       \
        xs[3][bp][nn] = make_ulonglong2(pk2(a1.z, c1.z), pk2(a1.w, c1.w));       \
    }

// ---------------------------------------------------------------------------
// k_sj: s partials. block = (n-chunk of 32, b-group of 16); 256 threads.
// Thread owns co pair (2t,2t+1); acc lanes are b-pairs; a0/a1 interleaved.
// ---------------------------------------------------------------------------
__global__ __launch_bounds__(256, 2)
void k_sj(const float* __restrict__ x, const float* __restrict__ W, int use_e)
{
    const int chunk = blockIdx.x;
    const int bg    = blockIdx.y;
    const int t     = threadIdx.x;
    const int n0    = chunk * NPC;
    const int c     = t >> 3;

    __shared__ ulonglong2 xs[4][BP][NPC];   // 16KB
    __shared__ float es[NPC * CC];          // 4KB

    const float4* x4 = (const float4*)x;
    XS_LOAD(xs, x4, bg, n0, t);
    if (use_e) {
        for (int idx = t; idx < NPC * CC; idx += 256)
            es[idx] = g_e[(size_t)n0 * CC + idx];
    }
    __syncthreads();

    u64 acc0[BP], acc1[BP];
#pragma unroll
    for (int bp = 0; bp < BP; bp++) { acc0[bp] = 0ull; acc1[bp] = 0ull; }

    const float4* wp = (const float4*)(W + (size_t)n0 * WROW + (size_t)(2 * t) * II);
    float4 wa0 = wp[0], wa1 = wp[1], wb0 = wp[2], wb1 = wp[3];

    for (int nn = 0; nn < NPC; nn++) {
        float cw = use_e ? es[nn * CC + c] : (1.0f / (float)NN);
        u64 wc0[8], wc1[8];
        {
            float m;
            m = wa0.x * cw; wc0[0] = pk2(m, m);
            m = wa0.y * cw; wc0[1] = pk2(m, m);
            m = wa0.z * cw; wc0[2] = pk2(m, m);
            m = wa0.w * cw; wc0[3] = pk2(m, m);
            m = wa1.x * cw; wc0[4] = pk2(m, m);
            m = wa1.y * cw; wc0[5] = pk2(m, m);
            m = wa1.z * cw; wc0[6] = pk2(m, m);
            m = wa1.w * cw; wc0[7] = pk2(m, m);
            m = wb0.x * cw; wc1[0] = pk2(m, m);
            m = wb0.y * cw; wc1[1] = pk2(m, m);
            m = wb0.z * cw; wc1[2] = pk2(m, m);
            m = wb0.w * cw; wc1[3] = pk2(m, m);
            m = wb1.x * cw; wc1[4] = pk2(m, m);
            m = wb1.y * cw; wc1[5] = pk2(m, m);
            m = wb1.z * cw; wc1[6] = pk2(m, m);
            m = wb1.w * cw; wc1[7] = pk2(m, m);
        }
        if (nn + 1 < NPC) {
            const float4* wn = wp + (size_t)(nn + 1) * (WROW / 4);
            wa0 = wn[0]; wa1 = wn[1]; wb0 = wn[2]; wb1 = wn[3];
        }
#pragma unroll
        for (int bp = 0; bp < BP; bp++) {
            ulonglong2 x01 = xs[0][bp][nn];
            ulonglong2 x23 = xs[1][bp][nn];
            ulonglong2 x45 = xs[2][bp][nn];
            ulonglong2 x67 = xs[3][bp][nn];
            u64 a0 = acc0[bp], a1 = acc1[bp];
            a0 = ffma2(wc0[0], x01.x, a0); a1 = ffma2(wc1[0], x01.x, a1);
            a0 = ffma2(wc0[1], x01.y, a0); a1 = ffma2(wc1[1], x01.y, a1);
            a0 = ffma2(wc0[2], x23.x, a0); a1 = ffma2(wc1[2], x23.x, a1);
            a0 = ffma2(wc0[3], x23.y, a0); a1 = ffma2(wc1[3], x23.y, a1);
            a0 = ffma2(wc0[4], x45.x, a0); a1 = ffma2(wc1[4], x45.x, a1);
            a0 = ffma2(wc0[5], x45.y, a0); a1 = ffma2(wc1[5], x45.y, a1);
            a0 = ffma2(wc0[6], x67.x, a0); a1 = ffma2(wc1[6], x67.x, a1);
            a0 = ffma2(wc0[7], x67.y, a0); a1 = ffma2(wc1[7], x67.y, a1);
            acc0[bp] = a0; acc1[bp] = a1;
        }
    }

    float* sp = g_spart + ((size_t)chunk * BB + (size_t)bg * BG) * CO + 2 * t;
#pragma unroll
    for (int bp = 0; bp < BP; bp++) {
        float2 f0 = unpk(acc0[bp]);   // (s[b0,co0], s[b1,co0])
        float2 f1 = unpk(acc1[bp]);   // (s[b0,co1], s[b1,co1])
        *(float2*)(sp + (size_t)(2 * bp) * CO)     = make_float2(f0.x, f1.x);
        *(float2*)(sp + (size_t)(2 * bp + 1) * CO) = make_float2(f0.y, f1.y);
    }
}

// ---------------------------------------------------------------------------
// k_bupd: agreement partials; recompute t per n, dot with v (b-pair packed).
// ---------------------------------------------------------------------------
__global__ __launch_bounds__(256, 2)
void k_bupd(const float* __restrict__ x, const float* __restrict__ W)
{
    const int chunk = blockIdx.x;
    const int bg    = blockIdx.y;
    const int t     = threadIdx.x;
    const int n0    = chunk * NPC;

    __shared__ ulonglong2 xs[4][BP][NPC];   // 16KB

    const float4* x4 = (const float4*)x;
    XS_LOAD(xs, x4, bg, n0, t);
    __syncthreads();

    u64 vp0[BP], vp1[BP];
#pragma unroll
    for (int bp = 0; bp < BP; bp++) {
        const float* v0 = g_v + (size_t)(bg * BG + 2 * bp) * CO + 2 * t;
        const float* v1 = g_v + (size_t)(bg * BG + 2 * bp + 1) * CO + 2 * t;
        float2 a = *(const float2*)v0;   // (v[b0,co0], v[b0,co1])
        float2 b = *(const float2*)v1;
        vp0[bp] = pk2(a.x, b.x);         // (v[b0,co0], v[b1,co0])
        vp1[bp] = pk2(a.y, b.y);         // (v[b0,co1], v[b1,co1])
    }

    const float4* wp = (const float4*)(W + (size_t)n0 * WROW + (size_t)(2 * t) * II);
    float4 wa0 = wp[0], wa1 = wp[1], wb0 = wp[2], wb1 = wp[3];

    for (int nn = 0; nn < NPC; nn++) {
        u64 wd0[8], wd1[8];
        wd0[0] = pk2(wa0.x, wa0.x); wd0[1] = pk2(wa0.y, wa0.y);
        wd0[2] = pk2(wa0.z, wa0.z); wd0[3] = pk2(wa0.w, wa0.w);
        wd0[4] = pk2(wa1.x, wa1.x); wd0[5] = pk2(wa1.y, wa1.y);
        wd0[6] = pk2(wa1.z, wa1.z); wd0[7] = pk2(wa1.w, wa1.w);
        wd1[0] = pk2(wb0.x, wb0.x); wd1[1] = pk2(wb0.y, wb0.y);
        wd1[2] = pk2(wb0.z, wb0.z); wd1[3] = pk2(wb0.w, wb0.w);
        wd1[4] = pk2(wb1.x, wb1.x); wd1[5] = pk2(wb1.y, wb1.y);
        wd1[6] = pk2(wb1.z, wb1.z); wd1[7] = pk2(wb1.w, wb1.w);
        if (nn + 1 < NPC) {
            const float4* wn = wp + (size_t)(nn + 1) * (WROW / 4);
            wa0 = wn[0]; wa1 = wn[1]; wb0 = wn[2]; wb1 = wn[3];
        }
        u64 pacc = 0ull;
#pragma unroll
        for (int bp = 0; bp < BP; bp++) {
            ulonglong2 x01 = xs[0][bp][nn];
            ulonglong2 x23 = xs[1][bp][nn];
            ulonglong2 x45 = xs[2][bp][nn];
            ulonglong2 x67 = xs[3][bp][nn];
            u64 t0 = fmul2(wd0[0], x01.x);
            u64 t1 = fmul2(wd1[0], x01.x);
            t0 = ffma2(wd0[1], x01.y, t0); t1 = ffma2(wd1[1], x01.y, t1);
            t0 = ffma2(wd0[2], x23.x, t0); t1 = ffma2(wd1[2], x23.x, t1);
            t0 = ffma2(wd0[3], x23.y, t0); t1 = ffma2(wd1[3], x23.y, t1);
            t0 = ffma2(wd0[4], x45.x, t0); t1 = ffma2(wd1[4], x45.x, t1);
            t0 = ffma2(wd0[5], x45.y, t0); t1 = ffma2(wd1[5], x45.y, t1);
            t0 = ffma2(wd0[6], x67.x, t0); t1 = ffma2(wd1[6], x67.x, t1);
            t0 = ffma2(wd0[7], x67.y, t0); t1 = ffma2(wd1[7], x67.y, t1);
            pacc = ffma2(t0, vp0[bp], pacc);
            pacc = ffma2(t1, vp1[bp], pacc);
        }
        float2 pv = unpk(pacc);
        float p = pv.x + pv.y;
        p += __shfl_down_sync(0xffffffffu, p, 4, 8);
        p += __shfl_down_sync(0xffffffffu, p, 2, 8);
        p += __shfl_down_sync(0xffffffffu, p, 1, 8);
        if ((t & 7) == 0)
            g_bupd[(size_t)bg * (NN * CC) + (size_t)(n0 + nn) * CC + (t >> 3)] = p;
    }
}

// ---------------------------------------------------------------------------
// k_squash: float2 partial reduce + squash. 16384 float2 ids, 128 blocks.
// ---------------------------------------------------------------------------
__global__ void k_squash(float* __restrict__ dout, int uniform, int final_pass)
{
    int id2 = blockIdx.x * 128 + threadIdx.x;   // 0..16383 (b*256 + co/2)
    const float2* sp = (const float2*)g_spart;
    float sx = 0.0f, sy = 0.0f;
#pragma unroll 8
    for (int ch = 0; ch < NCHUNK; ch++) {
        float2 p = sp[(size_t)ch * 16384 + id2];
        sx += p.x; sy += p.y;
    }
    int c = (id2 >> 3) & 31;
    float scale = uniform ? 1.0f : g_inv[c];
    sx *= scale; sy *= scale;
    float2 v;
    v.x = sx * fabsf(sx) / (1.0f + sx * sx);
    v.y = sy * fabsf(sy) / (1.0f + sy * sy);
    if (final_pass) ((float2*)dout)[id2] = v;
    else            ((float2*)g_v)[id2]  = v;
}

// ---------------------------------------------------------------------------
// k_bcomb: combine 4 agreement partials (coalesced), update b, e = exp(b),
// per-block partial e-sums per c. grid 288 x 256.
// ---------------------------------------------------------------------------
__global__ void k_bcomb(int iter0)
{
    const int t   = threadIdx.x;
    const int idx = blockIdx.x * 256 + t;     // n*32 + c

    float a = g_bupd[idx]
            + g_bupd[(size_t)NN * CC + idx]
            + g_bupd[(size_t)2 * NN * CC + idx]
            + g_bupd[(size_t)3 * NN * CC + idx];
    a *= (1.0f / (float)BB);

    float bb = iter0 ? a : (g_b[idx] + a);
    g_b[idx] = bb;
    float e = expf(bb);
    g_e[idx] = e;

    __shared__ float sred[256];
    sred[t] = e;
    __syncthreads();
    if (t < 32) {
        float s = 0.0f;
#pragma unroll
        for (int r = 0; r < 8; r++) s += sred[r * 32 + t];
        g_epart[blockIdx.x * 32 + t] = s;
    }
}

// ---------------------------------------------------------------------------
// k_esum: per-c total of e, store reciprocal.
// ---------------------------------------------------------------------------
__global__ void k_esum()
{
    const int c = blockIdx.x;
    const int t = threadIdx.x;
    __shared__ float red[256];
    float s = 0.0f;
    for (int i = t; i < 288; i += 256)
        s += g_epart[i * 32 + c];
    red[t] = s;
    __syncthreads();
    for (int off = 128; off > 0; off >>= 1) {
        if (t < off) red[t] += red[t + off];
        __syncthreads();
    }
    if (t == 0) g_inv[c] = 1.0f / red[0];
}

// ---------------------------------------------------------------------------
extern "C" void kernel_launch(void* const* d_in, const int* in_sizes, int n_in,
                              void* d_out, int out_size)
{
    const float* x = (const float*)d_in[0];   // [B, N, I]
    const float* W = (const float*)d_in[1];   // [N, C, O, I]
    float* out = (float*)d_out;               // [B, C, O, 1]

    dim3 g(NCHUNK, NBG);

    // iteration 0 (uniform weights 1/N inside k_sj)
    k_sj<<<g, 256>>>(x, W, 0);
    k_squash<<<128, 128>>>(out, 1, 0);
    k_bupd<<<g, 256>>>(x, W);
    k_bcomb<<<288, 256>>>(1);
    k_esum<<<32, 256>>>();

    // iteration 1 (weights = exp(b), normalized in squash)
    k_sj<<<g, 256>>>(x, W, 1);
    k_squash<<<128, 128>>>(out, 0, 0);
    k_bupd<<<g, 256>>>(x, W);
    k_bcomb<<<288, 256>>>(0);
    k_esum<<<32, 256>>>();

    // iteration 2 (final)
    k_sj<<<g, 256>>>(x, W, 1);
    k_squash<<<128, 128>>>(out, 0, 1);
}